// round 11
// baseline (speedup 1.0000x reference)
#include <cuda_runtime.h>
#include <cstdint>

#define Bv 256
#define Sv 2048
#define Tv 48

// -------- runtime format flags --------
__device__ int g_tags64;   // tags stored as int64 (JAX x64) vs int32
__device__ int g_mask32;   // mask stored as int32 (0/1 words) vs 1-byte bool

// -------- packed f32x2 helpers (sm_103a) --------
#define FMA2(d,a,b,c) asm("fma.rn.f32x2 %0, %1, %2, %3;" : "=l"(d) : "l"(a), "l"(b), "l"(c))
#define ADD2(d,a,b)   asm("add.rn.f32x2 %0, %1, %2;"     : "=l"(d) : "l"(a), "l"(b))
#define MUL2(d,a,b)   asm("mul.rn.f32x2 %0, %1, %2;"     : "=l"(d) : "l"(a), "l"(b))

static __device__ __forceinline__ unsigned long long pack2(float x, float y){
  unsigned long long r; asm("mov.b64 %0, {%1, %2};" : "=l"(r) : "f"(x), "f"(y)); return r;
}
static __device__ __forceinline__ void unpack2(float& x, float& y, unsigned long long v){
  asm("mov.b64 {%0, %1}, %2;" : "=f"(x), "=f"(y) : "l"(v));
}
static __device__ __forceinline__ float rcp_fast(float x){
  float r; asm("rcp.approx.f32 %0, %1;" : "=f"(r) : "f"(x)); return r;
}
static __device__ __forceinline__ int ld_mask(const void* mp, size_t idx, int m32){
  return m32 ? ((const int*)mp)[idx] : (int)((const unsigned char*)mp)[idx];
}

// Parallel format detection (one warp).
__global__ void __launch_bounds__(32) detect_fmt_kernel(
    const unsigned int* __restrict__ tw, const unsigned int* __restrict__ mw){
  const int L = threadIdx.x;
  unsigned int bad64 = 0, badm = 0;
  #pragma unroll
  for (int i = 1 + 2 * L; i < 256; i += 64) bad64 |= (tw[i] != 0u);
  #pragma unroll
  for (int i = L; i < 512; i += 32)         badm  |= (mw[i] > 1u);
  bad64 = __any_sync(0xffffffffu, bad64);
  badm  = __any_sync(0xffffffffu, badm);
  if (L == 0){ g_tags64 = !bad64; g_mask32 = !badm; }
}

// gold-path score for one batch element, one warp. Lane 0 returns -score.
static __device__ __forceinline__ float score_one(
    const float* em, const void* tagsv, const void* maskp,
    const float* trans, const float* startv, const float* endv,
    size_t mbase, int L, int m32)
{
  const long long* t64 = (const long long*)tagsv;
  const int*       t32 = (const int*)tagsv;
  const int is64 = g_tags64;

  float acc = 0.f;
  int cnt = 0;
  #pragma unroll 4
  for (int s = L; s < Sv; s += 32){
    int ts = is64 ? (int)t64[mbase + s] : t32[mbase + s];
    int m  = ld_mask(maskp, mbase + s, m32);
    cnt += m;
    if (s > 0 && m){
      int tp = is64 ? (int)t64[mbase + s - 1] : t32[mbase + s - 1];
      acc += trans[tp * Tv + ts] + em[s * Tv + ts];
    }
  }
  #pragma unroll
  for (int o = 16; o; o >>= 1){
    acc += __shfl_xor_sync(0xffffffffu, acc, o);
    cnt += __shfl_xor_sync(0xffffffffu, cnt, o);
  }
  float r = 0.f;
  if (L == 0){
    int tg0 = is64 ? (int)t64[mbase] : t32[mbase];
    float sc = startv[tg0] + em[tg0] + acc;
    int last = cnt - 1;
    int tl = is64 ? (int)t64[mbase + last] : t32[mbase + last];
    sc += endv[tl];
    r = -sc;
  }
  return r;
}

// ==== fused kernel: 3 warps, grid = Bv/2 ====
// warp 0: forward log-partition for TWO batch elements (bA=2*blk, bB=bA+1),
//         chains interleaved in one warp for ILP — the forward step was shown
//         latency-bound (issue ~14%), so independent chain B fills chain A's
//         stall shadows whatever their source. ecol registers (the dominant
//         cost) are SHARED: transitions are batch-independent.
// warp 1: gold-path score for bA;  warp 2: score for bB.
// Stable skip-and-reset normalization (cadence 4) with CURRENT-step d_0;
// emission factors prefetched 4 deep + precooked 1 step ahead (off-path).
__global__ void __launch_bounds__(96, 1) crf_fused_kernel(
    const float* __restrict__ em_all,
    const void* __restrict__ tagsv,
    const void* __restrict__ maskp,
    const float* __restrict__ trans,
    const float* __restrict__ startv,
    const float* __restrict__ endv,
    float* __restrict__ out)
{
  const int bA = 2 * blockIdx.x;
  const int bB = bA + 1;
  const int tid = threadIdx.x;
  const int wid = tid >> 5;
  const int L = tid & 31;
  const int m32 = g_mask32;
  const float* emA = em_all + (size_t)bA * (Sv * Tv);
  const float* emB = em_all + (size_t)bB * (Sv * Tv);
  const size_t mbaseA = (size_t)bA * Sv;
  const size_t mbaseB = (size_t)bB * Sv;

  __shared__ float4 pdupA[2][32];
  __shared__ float4 pdupB[2][32];
  __shared__ float s_score[2];
  __shared__ float s_norm[2];

  if (wid == 1){
    float r = score_one(emA, tagsv, maskp, trans, startv, endv, mbaseA, L, m32);
    if (L == 0) s_score[0] = r;
  } else if (wid == 2){
    float r = score_one(emB, tagsv, maskp, trans, startv, endv, mbaseB, L, m32);
    if (L == 0) s_score[1] = r;
  } else {
    // ---------------- warp 0: forward for bA and bB, interleaved ----------------
    const bool act = (L < 24);
    const int t0 = act ? 2 * L : 0;
    const int t1 = t0 + 1;

    // shared E columns: E[j][t] = exp(transitions[j][t])
    unsigned long long ecol[Tv];
    #pragma unroll
    for (int j = 0; j < Tv; ++j){
      float ex = __expf(trans[j * Tv + t0]);
      float ey = __expf(trans[j * Tv + t1]);
      ecol[j] = pack2(ex, ey);
    }

    // init both chains
    float a0A = startv[t0] + emA[t0];
    float a1A = startv[t1] + emA[t1];
    float a0B = startv[t0] + emB[t0];
    float a1B = startv[t1] + emB[t1];
    float arefA = __shfl_sync(0xffffffffu, a0A, 0);
    float arefB = __shfl_sync(0xffffffffu, a0B, 0);
    float p0A = __expf(a0A - arefA), p1A = __expf(a1A - arefA);
    float p0B = __expf(a0B - arefB), p1B = __expf(a1B - arefB);
    float MaccA = arefA, kcA = 0.f;
    float MaccB = arefB, kcB = 0.f;
    pdupA[0][L] = make_float4(p0A, p0A, p1A, p1A);
    pdupB[0][L] = make_float4(p0B, p0B, p1B, p1B);
    __syncwarp();

    // raw prefetch slots (steps 1..4), both chains
    float2 e2_0A = *(const float2*)(emA + 1 * Tv + t0);
    float2 e2_1A = *(const float2*)(emA + 2 * Tv + t0);
    float2 e2_2A = *(const float2*)(emA + 3 * Tv + t0);
    float2 e2_3A = *(const float2*)(emA + 4 * Tv + t0);
    float2 e2_0B = *(const float2*)(emB + 1 * Tv + t0);
    float2 e2_1B = *(const float2*)(emB + 2 * Tv + t0);
    float2 e2_2B = *(const float2*)(emB + 3 * Tv + t0);
    float2 e2_3B = *(const float2*)(emB + 4 * Tv + t0);
    float er_0A = emA[1 * Tv], er_1A = emA[2 * Tv], er_2A = emA[3 * Tv], er_3A = emA[4 * Tv];
    float er_0B = emB[1 * Tv], er_1B = emB[2 * Tv], er_2B = emB[3 * Tv], er_3B = emB[4 * Tv];
    bool m_0A = ld_mask(maskp, mbaseA + 1, m32) != 0;
    bool m_1A = ld_mask(maskp, mbaseA + 2, m32) != 0;
    bool m_2A = ld_mask(maskp, mbaseA + 3, m32) != 0;
    bool m_3A = ld_mask(maskp, mbaseA + 4, m32) != 0;
    bool m_0B = ld_mask(maskp, mbaseB + 1, m32) != 0;
    bool m_1B = ld_mask(maskp, mbaseB + 2, m32) != 0;
    bool m_2B = ld_mask(maskp, mbaseB + 3, m32) != 0;
    bool m_3B = ld_mask(maskp, mbaseB + 4, m32) != 0;

    unsigned long long eoffXA = pack2(__expf(e2_0A.x - er_0A), __expf(e2_0A.y - er_0A));
    unsigned long long eoffXB = pack2(__expf(e2_0B.x - er_0B), __expf(e2_0B.y - er_0B));
    float mupXA = er_0A, mupXB = er_0B;
    unsigned long long eoffYA = 0ull, eoffYB = 0ull;
    float mupYA = 0.f, mupYB = 0.f;
    int buf = 0;

    // One chain's step compute (no sync / buf toggle — shared across chains).
    #define FSTEP(EMP, MBP, PD, P0, P1, MAC, KC, E2K, ERK, MK, E2N, ERN, EOC, MUC, EOP, MUP, SCUR, DO_NORM) \
    {                                                                          \
      const bool m_ = MK;                                                      \
      const unsigned long long eoff_ = EOC;                                    \
      float mupd_ = MUC;                                                       \
      int sn_ = (SCUR) + 4; if (sn_ > Sv - 1) sn_ = Sv - 1;                    \
      E2K = *(const float2*)(EMP + (size_t)sn_ * Tv + t0);                     \
      ERK = EMP[(size_t)sn_ * Tv];                                             \
      MK  = ld_mask(maskp, MBP + sn_, m32) != 0;                               \
      EOP = pack2(__expf(E2N.x - ERN), __expf(E2N.y - ERN));                   \
      MUP = ERN;                                                               \
      unsigned long long acc0 = 0ull, acc1 = 0ull, acc2 = 0ull, acc3 = 0ull;   \
      const ulonglong2* pp_ = (const ulonglong2*)&PD[buf][0];                  \
      _Pragma("unroll")                                                        \
      for (int jj = 0; jj < 24; jj += 2){                                      \
        ulonglong2 va = pp_[jj];                                               \
        ulonglong2 vb = pp_[jj + 1];                                           \
        FMA2(acc0, va.x, ecol[2 * jj + 0], acc0);                              \
        FMA2(acc1, va.y, ecol[2 * jj + 1], acc1);                              \
        FMA2(acc2, vb.x, ecol[2 * jj + 2], acc2);                              \
        FMA2(acc3, vb.y, ecol[2 * jj + 3], acc3);                              \
      }                                                                        \
      ADD2(acc0, acc0, acc1);                                                  \
      ADD2(acc2, acc2, acc3);                                                  \
      ADD2(acc0, acc0, acc2);                                                  \
      unsigned long long q_;                                                   \
      MUL2(q_, acc0, eoff_);                                                   \
      if (DO_NORM){                                                            \
        float d0lo_, d0hi_; unpack2(d0lo_, d0hi_, acc0);                       \
        float dref_ = __shfl_sync(0xffffffffu, d0lo_, 0);                      \
        float r_ = rcp_fast(dref_);                                            \
        unsigned long long rd_ = pack2(r_, r_);                                \
        MUL2(q_, q_, rd_);                                                     \
        mupd_ += __logf(dref_);                                                \
      }                                                                        \
      float np0_, np1_; unpack2(np0_, np1_, q_);                               \
      P0 = m_ ? np0_ : P0;                                                     \
      P1 = m_ ? np1_ : P1;                                                     \
      float madd_ = m_ ? mupd_ : 0.f;                                          \
      float y_ = madd_ - KC;                                                   \
      float t_ = MAC + y_;                                                     \
      KC = (t_ - MAC) - y_;                                                    \
      MAC = t_;                                                                \
      PD[buf ^ 1][L] = make_float4(P0, P0, P1, P1);                            \
    }

    #define DSTEP(K, N, EX, MX, EY, MY, SCUR, DO_NORM)                                              \
      FSTEP(emA, mbaseA, pdupA, p0A, p1A, MaccA, kcA, e2_##K##A, er_##K##A, m_##K##A,               \
            e2_##N##A, er_##N##A, EX##A, MX##A, EY##A, MY##A, SCUR, DO_NORM)                        \
      FSTEP(emB, mbaseB, pdupB, p0B, p1B, MaccB, kcB, e2_##K##B, er_##K##B, m_##K##B,               \
            e2_##N##B, er_##N##B, EX##B, MX##B, EY##B, MY##B, SCUR, DO_NORM)                        \
      buf ^= 1;                                                                                     \
      __syncwarp();

    // 511 groups of 4 (s = 1..2044); norm on s%4==1. Then 3-step tail.
    #pragma unroll 1
    for (int g = 0; g < 511; ++g){
      const int s = 1 + 4 * g;
      DSTEP(0, 1, eoffX, mupX, eoffY, mupY, s + 0, true)
      DSTEP(1, 2, eoffY, mupY, eoffX, mupX, s + 1, false)
      DSTEP(2, 3, eoffX, mupX, eoffY, mupY, s + 2, false)
      DSTEP(3, 0, eoffY, mupY, eoffX, mupX, s + 3, false)
    }
    DSTEP(0, 1, eoffX, mupX, eoffY, mupY, 2045, true)
    DSTEP(1, 2, eoffY, mupY, eoffX, mupX, 2046, false)
    DSTEP(2, 3, eoffX, mupX, eoffY, mupY, 2047, false)
    #undef DSTEP
    #undef FSTEP

    // norm = M + log( sum_t p_t * exp(end_t) ), both chains
    float wA = 0.f, wB = 0.f;
    if (act){
      float ee0 = __expf(endv[t0]);
      float ee1 = __expf(endv[t1]);
      wA = p0A * ee0 + p1A * ee1;
      wB = p0B * ee0 + p1B * ee1;
    }
    #pragma unroll
    for (int o = 16; o; o >>= 1){
      wA += __shfl_xor_sync(0xffffffffu, wA, o);
      wB += __shfl_xor_sync(0xffffffffu, wB, o);
    }
    if (L == 0){
      s_norm[0] = (MaccA - kcA) + __logf(wA);
      s_norm[1] = (MaccB - kcB) + __logf(wB);
    }
  }

  __syncthreads();
  if (tid == 0){
    out[bA] = s_score[0] + s_norm[0];
    out[bB] = s_score[1] + s_norm[1];
  }
}

extern "C" void kernel_launch(void* const* d_in, const int* in_sizes, int n_in,
                              void* d_out, int out_size)
{
  const float* emissions       = (const float*)d_in[0];
  const void* tags             = d_in[1];
  const void* mask             = d_in[2];
  const float* trans           = (const float*)d_in[3];
  const float* startv          = (const float*)d_in[4];
  const float* endv            = (const float*)d_in[5];
  float* out                   = (float*)d_out;

  detect_fmt_kernel<<<1, 32>>>((const unsigned int*)tags, (const unsigned int*)mask);
  crf_fused_kernel<<<Bv / 2, 96>>>(emissions, tags, mask, trans, startv, endv, out);
}

// round 12
// speedup vs baseline: 1.8841x; 1.8841x over previous
#include <cuda_runtime.h>
#include <cstdint>

#define Bv 256
#define Sv 2048
#define Tv 48

// -------- runtime format flags --------
__device__ int g_tags64;   // tags stored as int64 (JAX x64) vs int32
__device__ int g_mask32;   // mask stored as int32 (0/1 words) vs 1-byte bool

// -------- packed f32x2 helpers (sm_103a) --------
#define FMA2(d,a,b,c) asm("fma.rn.f32x2 %0, %1, %2, %3;" : "=l"(d) : "l"(a), "l"(b), "l"(c))
#define ADD2(d,a,b)   asm("add.rn.f32x2 %0, %1, %2;"     : "=l"(d) : "l"(a), "l"(b))
#define MUL2(d,a,b)   asm("mul.rn.f32x2 %0, %1, %2;"     : "=l"(d) : "l"(a), "l"(b))

static __device__ __forceinline__ unsigned long long pack2(float x, float y){
  unsigned long long r; asm("mov.b64 %0, {%1, %2};" : "=l"(r) : "f"(x), "f"(y)); return r;
}
static __device__ __forceinline__ void unpack2(float& x, float& y, unsigned long long v){
  asm("mov.b64 {%0, %1}, %2;" : "=f"(x), "=f"(y) : "l"(v));
}
static __device__ __forceinline__ float rcp_fast(float x){
  float r; asm("rcp.approx.f32 %0, %1;" : "=f"(r) : "f"(x)); return r;
}
static __device__ __forceinline__ int ld_mask(const void* mp, size_t idx, int m32){
  return m32 ? ((const int*)mp)[idx] : (int)((const unsigned char*)mp)[idx];
}

// Parallel format detection (one warp).
__global__ void __launch_bounds__(32) detect_fmt_kernel(
    const unsigned int* __restrict__ tw, const unsigned int* __restrict__ mw){
  const int L = threadIdx.x;
  unsigned int bad64 = 0, badm = 0;
  #pragma unroll
  for (int i = 1 + 2 * L; i < 256; i += 64) bad64 |= (tw[i] != 0u);
  #pragma unroll
  for (int i = L; i < 512; i += 32)         badm  |= (mw[i] > 1u);
  bad64 = __any_sync(0xffffffffu, bad64);
  badm  = __any_sync(0xffffffffu, badm);
  if (L == 0){ g_tags64 = !bad64; g_mask32 = !badm; }
}

// ==== fused kernel: warp 0 = forward recurrence, warp 1 = gold-path score ====
// (R11 two-chain ILP reverted: wall time = per-chain latency; it also spilled.)
//
// Key change vs R10: the hot loop carries exactly ONE LDG class (the e2
// emission refill, 4 in flight <= 6 wbar slots). The mask is converted ONCE
// to a 64-word shared bitset (ballot), read per step as a uniform LDS.32;
// the normalizer em[s,0] comes from a shfl of lane 0's e2 slot (off-path
// cook). Rationale: with 3 LDG classes (12 loads in flight) + 24 LDS/step
// competing for 6 scoreboard slots, ptxas must co-assign DRAM-latency LDGs
// with 29-cyc LDSs; SB wait is max-of-arms, so matvec LDS consumers were
// being dragged to LDG latency — the unexplained ~190 cyc/step.
__global__ void __launch_bounds__(64, 1) crf_fused_kernel(
    const float* __restrict__ em_all,
    const void* __restrict__ tagsv,
    const void* __restrict__ maskp,
    const float* __restrict__ trans,
    const float* __restrict__ startv,
    const float* __restrict__ endv,
    float* __restrict__ out)
{
  const int b = blockIdx.x;
  const int tid = threadIdx.x;
  const int m32 = g_mask32;
  const float* em = em_all + (size_t)b * (Sv * Tv);
  const size_t mbase = (size_t)b * Sv;

  __shared__ float4 pdup[2][32];      // p broadcast, double-buffered, padded to 32
  __shared__ unsigned s_mbits[Sv/32]; // 2048-bit mask bitset (64 words)
  __shared__ float s_score;
  __shared__ float s_norm;

  if (tid >= 32){
    // ---------------- warp 1: gold-path score ----------------
    const int L = tid - 32;
    const long long* t64 = (const long long*)tagsv;
    const int*       t32 = (const int*)tagsv;
    const int is64 = g_tags64;

    float acc = 0.f;
    int cnt = 0;
    #pragma unroll 4
    for (int s = L; s < Sv; s += 32){
      int ts = is64 ? (int)t64[mbase + s] : t32[mbase + s];
      int m  = ld_mask(maskp, mbase + s, m32);
      cnt += m;
      if (s > 0 && m){
        int tp = is64 ? (int)t64[mbase + s - 1] : t32[mbase + s - 1];
        acc += trans[tp * Tv + ts] + em[s * Tv + ts];
      }
    }
    #pragma unroll
    for (int o = 16; o; o >>= 1){
      acc += __shfl_xor_sync(0xffffffffu, acc, o);
      cnt += __shfl_xor_sync(0xffffffffu, cnt, o);
    }
    if (L == 0){
      int tg0 = is64 ? (int)t64[mbase] : t32[mbase];
      float sc = startv[tg0] + em[tg0] + acc;
      int last = cnt - 1;
      int tl = is64 ? (int)t64[mbase + last] : t32[mbase + last];
      sc += endv[tl];
      s_score = -sc;
    }
  } else {
    // ---------------- warp 0: forward log-partition ----------------
    const int L = tid;
    const bool act = (L < 24);
    const int t0 = act ? 2 * L : 0;
    const int t1 = t0 + 1;

    // Build the mask bitset FIRST (one-time; coalesced loads + ballot).
    #pragma unroll 8
    for (int w = 0; w < Sv / 32; ++w){
      bool bit = ld_mask(maskp, mbase + (w * 32 + L), m32) != 0;
      unsigned word = __ballot_sync(0xffffffffu, bit);
      if (L == 0) s_mbits[w] = word;
    }

    // E columns for this lane's two tags: E[j][t] = exp(transitions[j][t])
    unsigned long long ecol[Tv];
    #pragma unroll
    for (int j = 0; j < Tv; ++j){
      float ex = __expf(trans[j * Tv + t0]);
      float ey = __expf(trans[j * Tv + t1]);
      ecol[j] = pack2(ex, ey);
    }

    // init: alpha0 = start + em[0,:]; normalize by alpha0[tag 0]
    float a0 = startv[t0] + em[t0];
    float a1 = startv[t1] + em[t1];
    float aref = __shfl_sync(0xffffffffu, a0, 0);
    float p0 = __expf(a0 - aref);
    float p1 = __expf(a1 - aref);
    float Macc = aref;   // Kahan float accumulator
    float kc = 0.f;
    pdup[0][L] = make_float4(p0, p0, p1, p1);
    __syncwarp();

    // raw emission prefetch slots (steps 1..4) — the ONLY hot-loop LDGs
    float2 e2_0 = *(const float2*)(em + 1 * Tv + t0);
    float2 e2_1 = *(const float2*)(em + 2 * Tv + t0);
    float2 e2_2 = *(const float2*)(em + 3 * Tv + t0);
    float2 e2_3 = *(const float2*)(em + 4 * Tv + t0);

    // bootstrap cooked pair X for step 1 (eoff = exp(em - em0), mup = em0)
    float eref0 = __shfl_sync(0xffffffffu, e2_0.x, 0);
    unsigned long long eoffX = pack2(__expf(e2_0.x - eref0), __expf(e2_0.y - eref0));
    float mupX = eref0;
    unsigned long long eoffY = 0ull;
    float mupY = 0.f;
    int buf = 0;

    // STEP at index SCUR: consumes cooked pair C; refills raw slot K with
    // step SCUR+4; cooks pair P for step SCUR+1 from slot N (loaded 3 steps
    // ago). Mask read from the shared bitset (uniform LDS, off-path).
    #define STEP(E2K, E2N, EOC, MUC, EOP, MUP, SCUR, DO_NORM)                 \
    {                                                                          \
      const unsigned mw_ = s_mbits[(SCUR) >> 5];                               \
      const bool m_ = (mw_ >> ((SCUR) & 31)) & 1u;                             \
      const unsigned long long eoff_ = EOC;                                    \
      float mupd_ = MUC;                                                       \
      int sn_ = (SCUR) + 4; if (sn_ > Sv - 1) sn_ = Sv - 1;                    \
      E2K = *(const float2*)(em + (size_t)sn_ * Tv + t0);                      \
      const float2 en_ = E2N;                                                  \
      float erefN_ = __shfl_sync(0xffffffffu, en_.x, 0);                       \
      EOP = pack2(__expf(en_.x - erefN_), __expf(en_.y - erefN_));             \
      MUP = erefN_;                                                            \
      unsigned long long acc0 = 0ull, acc1 = 0ull, acc2 = 0ull, acc3 = 0ull;   \
      const ulonglong2* pp_ = (const ulonglong2*)&pdup[buf][0];                \
      _Pragma("unroll")                                                        \
      for (int jj = 0; jj < 24; jj += 2){                                      \
        ulonglong2 va = pp_[jj];                                               \
        ulonglong2 vb = pp_[jj + 1];                                           \
        FMA2(acc0, va.x, ecol[2 * jj + 0], acc0);                              \
        FMA2(acc1, va.y, ecol[2 * jj + 1], acc1);                              \
        FMA2(acc2, vb.x, ecol[2 * jj + 2], acc2);                              \
        FMA2(acc3, vb.y, ecol[2 * jj + 3], acc3);                              \
      }                                                                        \
      ADD2(acc0, acc0, acc1);                                                  \
      ADD2(acc2, acc2, acc3);                                                  \
      ADD2(acc0, acc0, acc2);                                                  \
      unsigned long long q_;                                                   \
      MUL2(q_, acc0, eoff_);                                                   \
      if (DO_NORM){                                                            \
        float d0lo_, d0hi_; unpack2(d0lo_, d0hi_, acc0);                       \
        float dref_ = __shfl_sync(0xffffffffu, d0lo_, 0);                      \
        float r_ = rcp_fast(dref_);                                            \
        unsigned long long rd_ = pack2(r_, r_);                                \
        MUL2(q_, q_, rd_);                                                     \
        mupd_ += __logf(dref_);                                                \
      }                                                                        \
      float np0_, np1_; unpack2(np0_, np1_, q_);                               \
      p0 = m_ ? np0_ : p0;                                                     \
      p1 = m_ ? np1_ : p1;                                                     \
      float madd_ = m_ ? mupd_ : 0.f;                                          \
      float y_ = madd_ - kc;                                                   \
      float t_ = Macc + y_;                                                    \
      kc = (t_ - Macc) - y_;                                                   \
      Macc = t_;                                                               \
      pdup[buf ^ 1][L] = make_float4(p0, p0, p1, p1);                          \
      buf ^= 1;                                                                \
      __syncwarp();                                                            \
    }

    // 511 groups of 4 (s = 1..2044); norm on s%4==1. Then 3-step tail.
    #pragma unroll 1
    for (int g = 0; g < 511; ++g){
      const int s = 1 + 4 * g;
      STEP(e2_0, e2_1, eoffX, mupX, eoffY, mupY, s + 0, true)
      STEP(e2_1, e2_2, eoffY, mupY, eoffX, mupX, s + 1, false)
      STEP(e2_2, e2_3, eoffX, mupX, eoffY, mupY, s + 2, false)
      STEP(e2_3, e2_0, eoffY, mupY, eoffX, mupX, s + 3, false)
    }
    STEP(e2_0, e2_1, eoffX, mupX, eoffY, mupY, 2045, true)
    STEP(e2_1, e2_2, eoffY, mupY, eoffX, mupX, 2046, false)
    STEP(e2_2, e2_3, eoffX, mupX, eoffY, mupY, 2047, false)
    #undef STEP

    // norm = M + log( sum_t p_t * exp(end_t) )
    float w = 0.f;
    if (act) w = p0 * __expf(endv[t0]) + p1 * __expf(endv[t1]);
    #pragma unroll
    for (int o = 16; o; o >>= 1) w += __shfl_xor_sync(0xffffffffu, w, o);
    if (L == 0) s_norm = (Macc - kc) + __logf(w);
  }

  __syncthreads();
  if (tid == 0) out[b] = s_score + s_norm;
}

extern "C" void kernel_launch(void* const* d_in, const int* in_sizes, int n_in,
                              void* d_out, int out_size)
{
  const float* emissions       = (const float*)d_in[0];
  const void* tags             = d_in[1];
  const void* mask             = d_in[2];
  const float* trans           = (const float*)d_in[3];
  const float* startv          = (const float*)d_in[4];
  const float* endv            = (const float*)d_in[5];
  float* out                   = (float*)d_out;

  detect_fmt_kernel<<<1, 32>>>((const unsigned int*)tags, (const unsigned int*)mask);
  crf_fused_kernel<<<Bv, 64>>>(emissions, tags, mask, trans, startv, endv, out);
}

// round 17
// speedup vs baseline: 1.9429x; 1.0312x over previous
#include <cuda_runtime.h>
#include <cstdint>

#define Bv 256
#define Sv 2048
#define Tv 48
#define FULL 0xffffffffu

// -------- runtime format flags --------
__device__ int g_tags64;   // tags stored as int64 (JAX x64) vs int32
__device__ int g_mask32;   // mask stored as int32 (0/1 words) vs 1-byte bool

// -------- packed f32x2 helpers (sm_103a) --------
#define FMA2(d,a,b,c) asm("fma.rn.f32x2 %0, %1, %2, %3;" : "=l"(d) : "l"(a), "l"(b), "l"(c))
#define ADD2(d,a,b)   asm("add.rn.f32x2 %0, %1, %2;"     : "=l"(d) : "l"(a), "l"(b))
#define MUL2(d,a,b)   asm("mul.rn.f32x2 %0, %1, %2;"     : "=l"(d) : "l"(a), "l"(b))

static __device__ __forceinline__ unsigned long long pack2(float x, float y){
  unsigned long long r; asm("mov.b64 %0, {%1, %2};" : "=l"(r) : "f"(x), "f"(y)); return r;
}
static __device__ __forceinline__ void unpack2(float& x, float& y, unsigned long long v){
  asm("mov.b64 {%0, %1}, %2;" : "=f"(x), "=f"(y) : "l"(v));
}
static __device__ __forceinline__ float rcp_fast(float x){
  float r; asm("rcp.approx.f32 %0, %1;" : "=f"(r) : "f"(x)); return r;
}
static __device__ __forceinline__ int ld_mask(const void* mp, size_t idx, int m32){
  return m32 ? ((const int*)mp)[idx] : (int)((const unsigned char*)mp)[idx];
}

// Parallel format detection (one warp).
__global__ void __launch_bounds__(32) detect_fmt_kernel(
    const unsigned int* __restrict__ tw, const unsigned int* __restrict__ mw){
  const int L = threadIdx.x;
  unsigned int bad64 = 0, badm = 0;
  #pragma unroll
  for (int i = 1 + 2 * L; i < 256; i += 64) bad64 |= (tw[i] != 0u);
  #pragma unroll
  for (int i = L; i < 512; i += 32)         badm  |= (mw[i] > 1u);
  bad64 = __any_sync(FULL, bad64);
  badm  = __any_sync(FULL, badm);
  if (L == 0){ g_tags64 = !bad64; g_mask32 = !badm; }
}

// ==== fused kernel: warp 0 = forward recurrence, warp 1 = gold-path score ====
//
// R13 change: the p broadcast goes through REGISTER SHUFFLES, not shared
// memory. The per-step STS -> __syncwarp -> LDS round-trip (no store
// forwarding; the prime suspect for the ~190 unexplained cyc/step) is gone.
// Matvec restructure: FMA2 operand = (p_{2jj}, p_{2jj+1}) packed from two
// 32-bit shfls of lane jj; each lane keeps TWO accumulators for its own tags
// (t0, t1), each holding (even-j, odd-j) partial sums; a cross-half add at
// the end yields d_t0, d_t1. Same 48 FMA2 per step; no SMEM, no syncwarp —
// shfl_sync provides the converged exchange (p update precedes the shfl in
// program order on every lane).
__global__ void __launch_bounds__(64, 1) crf_fused_kernel(
    const float* __restrict__ em_all,
    const void* __restrict__ tagsv,
    const void* __restrict__ maskp,
    const float* __restrict__ trans,
    const float* __restrict__ startv,
    const float* __restrict__ endv,
    float* __restrict__ out)
{
  const int b = blockIdx.x;
  const int tid = threadIdx.x;
  const int m32 = g_mask32;
  const float* em = em_all + (size_t)b * (Sv * Tv);
  const size_t mbase = (size_t)b * Sv;

  __shared__ unsigned s_mbits[Sv/32]; // 2048-bit mask bitset (64 words)
  __shared__ float s_score;
  __shared__ float s_norm;

  if (tid >= 32){
    // ---------------- warp 1: gold-path score ----------------
    const int L = tid - 32;
    const long long* t64 = (const long long*)tagsv;
    const int*       t32 = (const int*)tagsv;
    const int is64 = g_tags64;

    float acc = 0.f;
    int cnt = 0;
    #pragma unroll 4
    for (int s = L; s < Sv; s += 32){
      int ts = is64 ? (int)t64[mbase + s] : t32[mbase + s];
      int m  = ld_mask(maskp, mbase + s, m32);
      cnt += m;
      if (s > 0 && m){
        int tp = is64 ? (int)t64[mbase + s - 1] : t32[mbase + s - 1];
        acc += trans[tp * Tv + ts] + em[s * Tv + ts];
      }
    }
    #pragma unroll
    for (int o = 16; o; o >>= 1){
      acc += __shfl_xor_sync(FULL, acc, o);
      cnt += __shfl_xor_sync(FULL, cnt, o);
    }
    if (L == 0){
      int tg0 = is64 ? (int)t64[mbase] : t32[mbase];
      float sc = startv[tg0] + em[tg0] + acc;
      int last = cnt - 1;
      int tl = is64 ? (int)t64[mbase + last] : t32[mbase + last];
      sc += endv[tl];
      s_score = -sc;
    }
  } else {
    // ---------------- warp 0: forward log-partition ----------------
    const int L = tid;
    const bool act = (L < 24);
    const int t0 = act ? 2 * L : 0;
    const int t1 = t0 + 1;

    // Build the mask bitset once (coalesced loads + ballot; off hot path).
    #pragma unroll 8
    for (int w = 0; w < Sv / 32; ++w){
      bool bit = ld_mask(maskp, mbase + (w * 32 + L), m32) != 0;
      unsigned word = __ballot_sync(FULL, bit);
      if (L == 0) s_mbits[w] = word;
    }

    // E pairs arranged for the shfl formulation:
    //   eT0[jj] = ( E[2jj][t0], E[2jj+1][t0] )   (pairs over j, fixed t)
    //   eT1[jj] = ( E[2jj][t1], E[2jj+1][t1] )
    unsigned long long eT0[24], eT1[24];
    #pragma unroll
    for (int jj = 0; jj < 24; ++jj){
      float a = __expf(trans[(2 * jj)     * Tv + t0]);
      float bq = __expf(trans[(2 * jj + 1) * Tv + t0]);
      float c = __expf(trans[(2 * jj)     * Tv + t1]);
      float dd = __expf(trans[(2 * jj + 1) * Tv + t1]);
      eT0[jj] = pack2(a, bq);
      eT1[jj] = pack2(c, dd);
    }

    // init: alpha0 = start + em[0,:]; normalize by alpha0[tag 0]
    float a0 = startv[t0] + em[t0];
    float a1 = startv[t1] + em[t1];
    float aref = __shfl_sync(FULL, a0, 0);
    float p0 = __expf(a0 - aref);   // lanes >= 24 hold junk; never read (jj < 24)
    float p1 = __expf(a1 - aref);
    float Macc = aref;   // Kahan float accumulator
    float kc = 0.f;

    // raw emission prefetch slots (steps 1..4) — the ONLY hot-loop LDGs
    float2 e2_0 = *(const float2*)(em + 1 * Tv + t0);
    float2 e2_1 = *(const float2*)(em + 2 * Tv + t0);
    float2 e2_2 = *(const float2*)(em + 3 * Tv + t0);
    float2 e2_3 = *(const float2*)(em + 4 * Tv + t0);

    // bootstrap cooked pair X for step 1 (eoff = exp(em - em0), mup = em0)
    float eref0 = __shfl_sync(FULL, e2_0.x, 0);
    unsigned long long eoffX = pack2(__expf(e2_0.x - eref0), __expf(e2_0.y - eref0));
    float mupX = eref0;
    unsigned long long eoffY = 0ull;
    float mupY = 0.f;

    // STEP at index SCUR: consumes cooked pair C; refills raw slot K with
    // step SCUR+4; cooks pair P for step SCUR+1 from slot N.
    #define STEP(E2K, E2N, EOC, MUC, EOP, MUP, SCUR, DO_NORM)                 \
    {                                                                          \
      const unsigned mw_ = s_mbits[(SCUR) >> 5];                               \
      const bool m_ = (mw_ >> ((SCUR) & 31)) & 1u;                             \
      const unsigned long long eoff_ = EOC;                                    \
      float mupd_ = MUC;                                                       \
      int sn_ = (SCUR) + 4; if (sn_ > Sv - 1) sn_ = Sv - 1;                    \
      E2K = *(const float2*)(em + (size_t)sn_ * Tv + t0);                      \
      const float2 en_ = E2N;                                                  \
      float erefN_ = __shfl_sync(FULL, en_.x, 0);                              \
      EOP = pack2(__expf(en_.x - erefN_), __expf(en_.y - erefN_));             \
      MUP = erefN_;                                                            \
      unsigned long long a0_ = 0ull, a1_ = 0ull;                               \
      _Pragma("unroll")                                                        \
      for (int jj = 0; jj < 24; ++jj){                                         \
        float plo_ = __shfl_sync(FULL, p0, jj);                                \
        float phi_ = __shfl_sync(FULL, p1, jj);                                \
        unsigned long long pj_ = pack2(plo_, phi_);                            \
        FMA2(a0_, pj_, eT0[jj], a0_);                                          \
        FMA2(a1_, pj_, eT1[jj], a1_);                                          \
      }                                                                        \
      float x0_, x1_, y0_, y1_;                                                \
      unpack2(x0_, x1_, a0_);                                                  \
      unpack2(y0_, y1_, a1_);                                                  \
      float d0_ = x0_ + x1_;                                                   \
      float d1_ = y0_ + y1_;                                                   \
      unsigned long long dq_ = pack2(d0_, d1_);                                \
      unsigned long long q_;                                                   \
      MUL2(q_, dq_, eoff_);                                                    \
      if (DO_NORM){                                                            \
        float dref_ = __shfl_sync(FULL, d0_, 0);                               \
        float r_ = rcp_fast(dref_);                                            \
        unsigned long long rd_ = pack2(r_, r_);                                \
        MUL2(q_, q_, rd_);                                                     \
        mupd_ += __logf(dref_);                                                \
      }                                                                        \
      float np0_, np1_; unpack2(np0_, np1_, q_);                               \
      p0 = m_ ? np0_ : p0;                                                     \
      p1 = m_ ? np1_ : p1;                                                     \
      float madd_ = m_ ? mupd_ : 0.f;                                          \
      float yk_ = madd_ - kc;                                                  \
      float tk_ = Macc + yk_;                                                  \
      kc = (tk_ - Macc) - yk_;                                                 \
      Macc = tk_;                                                              \
    }

    // 511 groups of 4 (s = 1..2044); norm on s%4==1. Then 3-step tail.
    #pragma unroll 1
    for (int g = 0; g < 511; ++g){
      const int s = 1 + 4 * g;
      STEP(e2_0, e2_1, eoffX, mupX, eoffY, mupY, s + 0, true)
      STEP(e2_1, e2_2, eoffY, mupY, eoffX, mupX, s + 1, false)
      STEP(e2_2, e2_3, eoffX, mupX, eoffY, mupY, s + 2, false)
      STEP(e2_3, e2_0, eoffY, mupY, eoffX, mupX, s + 3, false)
    }
    STEP(e2_0, e2_1, eoffX, mupX, eoffY, mupY, 2045, true)
    STEP(e2_1, e2_2, eoffY, mupY, eoffX, mupX, 2046, false)
    STEP(e2_2, e2_3, eoffX, mupX, eoffY, mupY, 2047, false)
    #undef STEP

    // norm = M + log( sum_t p_t * exp(end_t) )
    float w = 0.f;
    if (act) w = p0 * __expf(endv[t0]) + p1 * __expf(endv[t1]);
    #pragma unroll
    for (int o = 16; o; o >>= 1) w += __shfl_xor_sync(FULL, w, o);
    if (L == 0) s_norm = (Macc - kc) + __logf(w);
  }

  __syncthreads();
  if (tid == 0) out[b] = s_score + s_norm;
}

extern "C" void kernel_launch(void* const* d_in, const int* in_sizes, int n_in,
                              void* d_out, int out_size)
{
  const float* emissions       = (const float*)d_in[0];
  const void* tags             = d_in[1];
  const void* mask             = d_in[2];
  const float* trans           = (const float*)d_in[3];
  const float* startv          = (const float*)d_in[4];
  const float* endv            = (const float*)d_in[5];
  float* out                   = (float*)d_out;

  detect_fmt_kernel<<<1, 32>>>((const unsigned int*)tags, (const unsigned int*)mask);
  crf_fused_kernel<<<Bv, 64>>>(emissions, tags, mask, trans, startv, endv, out);
}